// round 14
// baseline (speedup 1.0000x reference)
#include <cuda_runtime.h>
#include <cuda_bf16.h>
#include <cstdint>

#define NB   16
#define CIN  512
#define NQ   4096
#define NPIX (NB*NQ)
#define NKEY 1024
#define DQK  64
#define DV   256
#define NCAT 384

// ---------------- scratch ----------------
__device__ __nv_bfloat16 g_wcat [CIN*NCAT];
__device__ float         g_bcat [NCAT];
__device__ __nv_bfloat16 g_wob  [DV*CIN];
__device__ __nv_bfloat16 g_thetab[NPIX*DQK];
__device__ __nv_bfloat16 g_phiPb [NB*NKEY*DQK];
__device__ __nv_bfloat16 g_gPb   [NB*NKEY*DV];
__device__ __nv_bfloat16 g_agb   [NPIX*DV];

// ---------------- PTX helpers ----------------
__device__ __forceinline__ uint32_t smem_u32(const void* p) {
    return (uint32_t)__cvta_generic_to_shared(p);
}
__device__ __forceinline__ void ldsm_x4(uint32_t& r0, uint32_t& r1, uint32_t& r2, uint32_t& r3, uint32_t a) {
    asm volatile("ldmatrix.sync.aligned.m8n8.x4.shared.b16 {%0,%1,%2,%3},[%4];\n"
                 : "=r"(r0), "=r"(r1), "=r"(r2), "=r"(r3) : "r"(a));
}
__device__ __forceinline__ void ldsm_x4t(uint32_t& r0, uint32_t& r1, uint32_t& r2, uint32_t& r3, uint32_t a) {
    asm volatile("ldmatrix.sync.aligned.m8n8.x4.trans.shared.b16 {%0,%1,%2,%3},[%4];\n"
                 : "=r"(r0), "=r"(r1), "=r"(r2), "=r"(r3) : "r"(a));
}
__device__ __forceinline__ void ldsm_x2t(uint32_t& r0, uint32_t& r1, uint32_t a) {
    asm volatile("ldmatrix.sync.aligned.m8n8.x2.trans.shared.b16 {%0,%1},[%2];\n"
                 : "=r"(r0), "=r"(r1) : "r"(a));
}
__device__ __forceinline__ void mma_bf16(float* c, const uint32_t* a, const uint32_t* b) {
    asm volatile("mma.sync.aligned.m16n8k16.row.col.f32.bf16.bf16.f32 "
                 "{%0,%1,%2,%3},{%4,%5,%6,%7},{%8,%9},{%0,%1,%2,%3};\n"
                 : "+f"(c[0]), "+f"(c[1]), "+f"(c[2]), "+f"(c[3])
                 : "r"(a[0]), "r"(a[1]), "r"(a[2]), "r"(a[3]), "r"(b[0]), "r"(b[1]));
}
__device__ __forceinline__ void cp16(uint32_t dst, const void* src) {
    asm volatile("cp.async.ca.shared.global [%0],[%1],16;\n" :: "r"(dst), "l"(src));
}
__device__ __forceinline__ void cp8(uint32_t dst, const void* src) {
    asm volatile("cp.async.ca.shared.global [%0],[%1],8;\n" :: "r"(dst), "l"(src));
}
__device__ __forceinline__ void cp_commit() { asm volatile("cp.async.commit_group;\n" ::: "memory"); }
__device__ __forceinline__ void cp_wait0()  { asm volatile("cp.async.wait_group 0;\n" ::: "memory"); }
__device__ __forceinline__ uint32_t packbf2(float a, float b) {
    __nv_bfloat162 h = __floats2bfloat162_rn(a, b);
    return *(uint32_t*)&h;
}

// ---------------- weight prep: concat + bf16 ----------------
__global__ void prep_k(const float* __restrict__ wt, const float* __restrict__ wp,
                       const float* __restrict__ wg, const float* __restrict__ bt,
                       const float* __restrict__ bp, const float* __restrict__ bg,
                       const float* __restrict__ wo,
                       __nv_bfloat16* __restrict__ wcat, float* __restrict__ bcat,
                       __nv_bfloat16* __restrict__ wob)
{
    int i = blockIdx.x * 256 + threadIdx.x;
    if (i < CIN * NCAT) {
        int r = i / NCAT, c = i % NCAT;
        float v = (c < 64) ? wt[r * 64 + c] : (c < 128 ? wp[r * 64 + c - 64] : wg[r * 256 + c - 128]);
        wcat[i] = __float2bfloat16(v);
    }
    if (i < NCAT) bcat[i] = (i < 64) ? bt[i] : (i < 128 ? bp[i - 64] : bg[i - 128]);
    if (i < DV * CIN) wob[i] = __float2bfloat16(wo[i]);
}

// ---------------- fused projection GEMM + bias + pool (mma.sync, R7 proven) ----------------
#define P_ASTR 40
#define P_WSTR 136
#define P_TS   136

__global__ void __launch_bounds__(256) proj_k(
    const float* __restrict__ X, const __nv_bfloat16* __restrict__ Wc,
    const float* __restrict__ bcat, __nv_bfloat16* __restrict__ thetab,
    __nv_bfloat16* __restrict__ phiPb, __nv_bfloat16* __restrict__ gPb)
{
    constexpr int BK = 32;
    __shared__ __align__(16) __nv_bfloat16 sm[2 * 128 * P_ASTR + 2 * BK * P_WSTR];
    __nv_bfloat16* As[2] = { sm, sm + 128 * P_ASTR };
    __nv_bfloat16* Ws[2] = { sm + 2 * 128 * P_ASTR, sm + 2 * 128 * P_ASTR + BK * P_WSTR };
    __nv_bfloat16* T = sm;

    const int tid = threadIdx.x, lane = tid & 31, wid = tid >> 5;
    const int wr = wid >> 2, wc = wid & 3;
    const int bn = blockIdx.x * 128;
    const int bm = blockIdx.y * 128;

    const int arow = tid >> 1, aq = (tid & 1) * 16;
    const float* Ap = X + (size_t)(bm + arow) * CIN + aq;
    const int wrow = tid >> 4, wcol = (tid & 15) * 8;
    const __nv_bfloat16* Wp = Wc + (size_t)wrow * NCAT + bn + wcol;

    uint32_t as_u[2] = { smem_u32(As[0]), smem_u32(As[1]) };
    uint32_t ws_u[2] = { smem_u32(Ws[0]), smem_u32(Ws[1]) };

    float4 ar[4];
    float acc[4][4][4];
#pragma unroll
    for (int mt = 0; mt < 4; mt++)
#pragma unroll
        for (int nt = 0; nt < 4; nt++)
#pragma unroll
            for (int i = 0; i < 4; i++) acc[mt][nt][i] = 0.f;

    auto ldgA = [&](int it) {
#pragma unroll
        for (int j = 0; j < 4; j++) ar[j] = *(const float4*)(Ap + it * BK + j * 4);
    };
    auto stsA = [&](int s) {
#pragma unroll
        for (int j = 0; j < 4; j++) {
            __nv_bfloat162 lo = __floats2bfloat162_rn(ar[j].x, ar[j].y);
            __nv_bfloat162 hi = __floats2bfloat162_rn(ar[j].z, ar[j].w);
            *(uint2*)&As[s][arow * P_ASTR + aq + j * 4] =
                make_uint2(*(uint32_t*)&lo, *(uint32_t*)&hi);
        }
    };
    auto cpW = [&](int s, int it) {
        const __nv_bfloat16* src = Wp + (size_t)it * BK * NCAT;
        cp16(ws_u[s] + (wrow * P_WSTR + wcol) * 2, src);
        cp16(ws_u[s] + ((wrow + 16) * P_WSTR + wcol) * 2, src + (size_t)16 * NCAT);
    };
    auto compute = [&](int s) {
#pragma unroll
        for (int ks = 0; ks < 2; ks++) {
            uint32_t af[4][4], bfr[4][2];
#pragma unroll
            for (int mt = 0; mt < 4; mt++)
                ldsm_x4(af[mt][0], af[mt][1], af[mt][2], af[mt][3],
                        as_u[s] + ((wr * 64 + mt * 16 + (lane & 15)) * P_ASTR + ks * 16 + (lane >> 4) * 8) * 2);
#pragma unroll
            for (int nt = 0; nt < 4; nt++)
                ldsm_x2t(bfr[nt][0], bfr[nt][1],
                         ws_u[s] + ((ks * 16 + (lane & 15)) * P_WSTR + wc * 32 + nt * 8) * 2);
#pragma unroll
            for (int mt = 0; mt < 4; mt++)
#pragma unroll
                for (int nt = 0; nt < 4; nt++)
                    mma_bf16(acc[mt][nt], af[mt], bfr[nt]);
        }
    };

    constexpr int nIt = CIN / BK;
    ldgA(0); cpW(0, 0); cp_commit(); stsA(0);
    cp_wait0(); __syncthreads();
    for (int it = 0; it < nIt; it++) {
        int cur = it & 1, nx = cur ^ 1;
        bool more = (it + 1 < nIt);
        if (more) { ldgA(it + 1); cpW(nx, it + 1); cp_commit(); }
        compute(cur);
        if (more) { stsA(nx); cp_wait0(); __syncthreads(); }
    }
    __syncthreads();

#pragma unroll
    for (int mt = 0; mt < 4; mt++) {
        int r0 = wr * 64 + mt * 16 + (lane >> 2);
#pragma unroll
        for (int nt = 0; nt < 4; nt++) {
            int col = wc * 32 + nt * 8 + (lane & 3) * 2;
            float b0 = bcat[bn + col], b1 = bcat[bn + col + 1];
            *(__nv_bfloat162*)&T[r0 * P_TS + col] =
                __floats2bfloat162_rn(acc[mt][nt][0] + b0, acc[mt][nt][1] + b1);
            *(__nv_bfloat162*)&T[(r0 + 8) * P_TS + col] =
                __floats2bfloat162_rn(acc[mt][nt][2] + b0, acc[mt][nt][3] + b1);
        }
    }
    __syncthreads();

    const int b  = bm >> 12;
    const int h2 = (bm & 4095) >> 7;
    const size_t keyb = (size_t)b * NKEY + h2 * 32;

    if (bn == 0) {
#pragma unroll
        for (int i = 0; i < 4; i++) {
            int e = tid + i * 256, row = e >> 3, c = (e & 7) * 8;
            *(uint4*)(thetab + (size_t)(bm + row) * DQK + c) = *(uint4*)&T[row * P_TS + c];
        }
#pragma unroll
        for (int i = 0; i < 8; i++) {
            int e = tid + i * 256, w2 = e >> 6, c = e & 63;
            int col = 64 + c, r0 = 2 * w2;
            float v0 = __bfloat162float(T[r0 * P_TS + col]);
            float v1 = __bfloat162float(T[(r0 + 1) * P_TS + col]);
            float v2 = __bfloat162float(T[(r0 + 64) * P_TS + col]);
            float v3 = __bfloat162float(T[(r0 + 65) * P_TS + col]);
            phiPb[(keyb + w2) * DQK + c] = __float2bfloat16(fmaxf(fmaxf(v0, v1), fmaxf(v2, v3)));
        }
    } else {
        int gc0 = bn - 128;
#pragma unroll
        for (int i = 0; i < 16; i++) {
            int e = tid + i * 256, w2 = e >> 7, c = e & 127;
            int r0 = 2 * w2;
            float v0 = __bfloat162float(T[r0 * P_TS + c]);
            float v1 = __bfloat162float(T[(r0 + 1) * P_TS + c]);
            float v2 = __bfloat162float(T[(r0 + 64) * P_TS + c]);
            float v3 = __bfloat162float(T[(r0 + 65) * P_TS + c]);
            gPb[(keyb + w2) * DV + gc0 + c] = __float2bfloat16(fmaxf(fmaxf(v0, v1), fmaxf(v2, v3)));
        }
    }
}

// ---------------- out-projection (R7 BM=128 version, reverted) ----------------
__global__ void __launch_bounds__(256, 2) outp_k(
    const __nv_bfloat16* __restrict__ A, const __nv_bfloat16* __restrict__ W,
    const float* __restrict__ bias, float* __restrict__ Out,
    const float* __restrict__ X, const float* __restrict__ sigma)
{
    constexpr int BK = 32, N = CIN, K = DV;
    __shared__ __align__(16) __nv_bfloat16 As[2][128 * P_ASTR];
    __shared__ __align__(16) __nv_bfloat16 Ws[2][BK * P_WSTR];

    const int tid = threadIdx.x, lane = tid & 31, wid = tid >> 5;
    const int wr = wid >> 2, wc = wid & 3;
    const int bn = blockIdx.x * 128;
    const int bm = blockIdx.y * 128;

    const int wrow = tid >> 4, wcol = (tid & 15) * 8;
    const __nv_bfloat16* Wp = W + (size_t)wrow * N + bn + wcol;

    uint32_t as_u[2] = { smem_u32(As[0]), smem_u32(As[1]) };
    uint32_t ws_u[2] = { smem_u32(Ws[0]), smem_u32(Ws[1]) };

    float acc[4][4][4];
#pragma unroll
    for (int mt = 0; mt < 4; mt++)
#pragma unroll
        for (int nt = 0; nt < 4; nt++)
#pragma unroll
            for (int i = 0; i < 4; i++) acc[mt][nt][i] = 0.f;

    auto cpA = [&](int s, int it) {
#pragma unroll
        for (int i = 0; i < 4; i++) {
            int ci = tid + i * 256, row = ci >> 3, c4 = (ci & 7) * 4;
            cp8(as_u[s] + (row * P_ASTR + c4) * 2,
                A + (size_t)(bm + row) * K + it * BK + c4);
        }
    };
    auto cpW = [&](int s, int it) {
        const __nv_bfloat16* src = Wp + (size_t)it * BK * N;
        cp16(ws_u[s] + (wrow * P_WSTR + wcol) * 2, src);
        cp16(ws_u[s] + ((wrow + 16) * P_WSTR + wcol) * 2, src + (size_t)16 * N);
    };
    auto compute = [&](int s) {
#pragma unroll
        for (int ks = 0; ks < 2; ks++) {
            uint32_t af[4][4], bfr[4][2];
#pragma unroll
            for (int mt = 0; mt < 4; mt++)
                ldsm_x4(af[mt][0], af[mt][1], af[mt][2], af[mt][3],
                        as_u[s] + ((wr * 64 + mt * 16 + (lane & 15)) * P_ASTR + ks * 16 + (lane >> 4) * 8) * 2);
#pragma unroll
            for (int nt = 0; nt < 4; nt++)
                ldsm_x2t(bfr[nt][0], bfr[nt][1],
                         ws_u[s] + ((ks * 16 + (lane & 15)) * P_WSTR + wc * 32 + nt * 8) * 2);
#pragma unroll
            for (int mt = 0; mt < 4; mt++)
#pragma unroll
                for (int nt = 0; nt < 4; nt++)
                    mma_bf16(acc[mt][nt], af[mt], bfr[nt]);
        }
    };

    constexpr int nIt = K / BK;
    cpA(0, 0); cpW(0, 0); cp_commit();
    cp_wait0(); __syncthreads();
    for (int it = 0; it < nIt; it++) {
        int cur = it & 1, nx = cur ^ 1;
        bool more = (it + 1 < nIt);
        if (more) { cpA(nx, it + 1); cpW(nx, it + 1); cp_commit(); }
        compute(cur);
        if (more) { cp_wait0(); __syncthreads(); }
    }

    const float s = sigma[0];
#pragma unroll
    for (int mt = 0; mt < 4; mt++) {
        int r0 = bm + wr * 64 + mt * 16 + (lane >> 2);
        float2 xv[4][2];
#pragma unroll
        for (int nt = 0; nt < 4; nt++) {
            int col = bn + wc * 32 + nt * 8 + (lane & 3) * 2;
#pragma unroll
            for (int h = 0; h < 2; h++)
                xv[nt][h] = *(const float2*)(X + (size_t)(r0 + h * 8) * N + col);
        }
#pragma unroll
        for (int nt = 0; nt < 4; nt++) {
            int col = bn + wc * 32 + nt * 8 + (lane & 3) * 2;
            float b0 = bias[col], b1 = bias[col + 1];
#pragma unroll
            for (int h = 0; h < 2; h++) {
                size_t off = (size_t)(r0 + h * 8) * N + col;
                *(float2*)(Out + off) = make_float2(xv[nt][h].x + s * (acc[mt][nt][2 * h] + b0),
                                                    xv[nt][h].y + s * (acc[mt][nt][2 * h + 1] + b1));
            }
        }
    }
}

// ---------------- flash attention: register-resident P, 1 sync/iter ----------------
// Warp (wr 0..3 = 16-row group, wh 0..1 = 128-value-col half).
// Each warp: S for its 16 rows x ALL 64 keys (dup across wh), exp+pack in regs -> PV.
// smem: phi[2] 64x72 bf16 | g[2] 64x264 bf16  (theta staged via phi[0] before loop)
#define F2_PH0  0
#define F2_PH1  9216
#define F2_G0   18432
#define F2_GSZ  33792
#define FATTN_SMEM (F2_G0 + 2*F2_GSZ)    // 86016

__global__ void __launch_bounds__(256, 2) fattn_k(
    const __nv_bfloat16* __restrict__ theta, const __nv_bfloat16* __restrict__ phiP,
    const __nv_bfloat16* __restrict__ gP, __nv_bfloat16* __restrict__ outg)
{
    extern __shared__ char smc[];
    const uint32_t base = smem_u32(smc);
    const uint32_t ph_u[2] = { base + F2_PH0, base + F2_PH1 };
    const uint32_t gs_u[2] = { base + F2_G0,  base + F2_G0 + F2_GSZ };

    const int b = blockIdx.y, q0 = blockIdx.x * 64;
    const int tid = threadIdx.x, lane = tid & 31, wid = tid >> 5;
    const int wr = wid & 3;          // 16-row group
    const int wh = wid >> 2;         // value-col half
    const int vc = wh * 128;

    const __nv_bfloat16* phb = phiP + (size_t)b * NKEY * DQK;
    const __nv_bfloat16* gb  = gP   + (size_t)b * NKEY * DV;

    // stage theta [64,64] into phi[0] region, load persistent A-frags
    {
        __nv_bfloat16* Th = (__nv_bfloat16*)smc;
#pragma unroll
        for (int i = 0; i < 2; i++) {
            int c = tid + i * 256, row = c >> 3, c8 = (c & 7) * 8;
            *(uint4*)&Th[row * 72 + c8] =
                *(const uint4*)(theta + ((size_t)b * NQ + q0 + row) * DQK + c8);
        }
    }
    __syncthreads();
    uint32_t af[4][4];
#pragma unroll
    for (int ks = 0; ks < 4; ks++)
        ldsm_x4(af[ks][0], af[ks][1], af[ks][2], af[ks][3],
                ph_u[0] + ((wr * 16 + (lane & 15)) * 72 + ks * 16 + (lane >> 4) * 8) * 2);
    __syncthreads();   // done reading theta; phi[0] may be overwritten

    auto ldPhi = [&](int buf, int kt) {
#pragma unroll
        for (int i = 0; i < 2; i++) {
            int c = tid + i * 256, row = c >> 3, c8 = (c & 7) * 8;
            cp16(ph_u[buf] + (row * 72 + c8) * 2, phb + (size_t)(kt * 64 + row) * DQK + c8);
        }
    };
    auto ldG = [&](int buf, int kt) {
#pragma unroll
        for (int i = 0; i < 8; i++) {
            int c = tid + i * 256, row = c >> 5, c8 = (c & 31) * 8;
            cp16(gs_u[buf] + (row * 264 + c8) * 2, gb + (size_t)(kt * 64 + row) * DV + c8);
        }
    };

    float l0 = 0.f, l1 = 0.f;
    float acc[16][4];                // 16 rows x 128 cols (16 n-frags)
#pragma unroll
    for (int nt = 0; nt < 16; nt++)
#pragma unroll
        for (int i = 0; i < 4; i++) acc[nt][i] = 0.f;

    // S B-frag address (x4: two n8-frags of pair np, k16 of step ks)
    const int sb_row = (lane >> 4) * 8 + (lane & 7);
    const int sb_col = ((lane >> 3) & 1) * 8;
    // PV g B-frag address (x4.trans: rows k16 of step ks, two col8-frags)
    const int gv_row = lane & 15;
    const int gv_col = vc + (lane >> 4) * 8;

    ldPhi(0, 0); ldG(0, 0); cp_commit();

    for (int kt = 0; kt < 16; kt++) {
        const int cur = kt & 1, nx = cur ^ 1;
        cp_wait0();
        __syncthreads();
        if (kt < 15) { ldPhi(nx, kt + 1); ldG(nx, kt + 1); cp_commit(); }

        // process key pairs: S (2 n-frags) -> exp/pack -> PV (k-frag np)
#pragma unroll
        for (int np = 0; np < 4; np++) {
            float s0[4] = {0.f, 0.f, 0.f, 0.f}, s1[4] = {0.f, 0.f, 0.f, 0.f};
#pragma unroll
            for (int ks = 0; ks < 4; ks++) {
                uint32_t b0, b1, b2, b3;
                ldsm_x4(b0, b1, b2, b3,
                        ph_u[cur] + ((np * 16 + sb_row) * 72 + ks * 16 + sb_col) * 2);
                uint32_t bl[2] = { b0, b1 }, bh[2] = { b2, b3 };
                mma_bf16(s0, af[ks], bl);
                mma_bf16(s1, af[ks], bh);
            }
            // exp + pack into PV A-fragment (k-frag np); accumulate row sums
            float e00 = __expf(s0[0]), e01 = __expf(s0[1]);
            float e02 = __expf(s0[2]), e03 = __expf(s0[3]);
            float e10 = __expf(s1[0]), e11 = __expf(s1[1]);
            float e12 = __expf(s1[2]), e13 = __expf(s1[3]);
            l0 += e00 + e01 + e10 + e11;
            l1 += e02 + e03 + e12 + e13;
            uint32_t aP[4];
            aP[0] = packbf2(e00, e01);   // (row,   k 0-7 of frag)
            aP[1] = packbf2(e02, e03);   // (row+8, k 0-7)
            aP[2] = packbf2(e10, e11);   // (row,   k 8-15)
            aP[3] = packbf2(e12, e13);   // (row+8, k 8-15)

            // PV: keys np*16..+16 x this warp's 128 value cols
#pragma unroll
            for (int nb = 0; nb < 8; nb++) {
                uint32_t g0, g1, g2, g3;
                ldsm_x4t(g0, g1, g2, g3,
                         gs_u[cur] + ((np * 16 + gv_row) * 264 + gv_col + nb * 16) * 2);
                uint32_t bl[2] = { g0, g1 }, bh[2] = { g2, g3 };
                mma_bf16(acc[2 * nb],     aP, bl);
                mma_bf16(acc[2 * nb + 1], aP, bh);
            }
        }
    }

    // row-sum reduce within quad (each warp computed full 1024-key sums)
    l0 += __shfl_xor_sync(0xffffffffu, l0, 1);
    l0 += __shfl_xor_sync(0xffffffffu, l0, 2);
    l1 += __shfl_xor_sync(0xffffffffu, l1, 1);
    l1 += __shfl_xor_sync(0xffffffffu, l1, 2);
    const float inv0 = 1.f / l0, inv1 = 1.f / l1;

    // epilogue
    const size_t rb = (size_t)b * NQ + q0 + wr * 16 + (lane >> 2);
#pragma unroll
    for (int nt = 0; nt < 16; nt++) {
        int col = vc + nt * 8 + (lane & 3) * 2;
        *(__nv_bfloat162*)&outg[rb * DV + col] =
            __floats2bfloat162_rn(acc[nt][0] * inv0, acc[nt][1] * inv0);
        *(__nv_bfloat162*)&outg[(rb + 8) * DV + col] =
            __floats2bfloat162_rn(acc[nt][2] * inv1, acc[nt][3] * inv1);
    }
}

// ---------------- launch ----------------
extern "C" void kernel_launch(void* const* d_in, const int* in_sizes, int n_in,
                              void* d_out, int out_size)
{
    const float* x       = (const float*)d_in[0];
    const float* w_theta = (const float*)d_in[1];
    const float* b_theta = (const float*)d_in[2];
    const float* w_phi   = (const float*)d_in[3];
    const float* b_phi   = (const float*)d_in[4];
    const float* w_g     = (const float*)d_in[5];
    const float* b_g     = (const float*)d_in[6];
    const float* w_o     = (const float*)d_in[7];
    const float* b_o     = (const float*)d_in[8];
    const float* sigma   = (const float*)d_in[9];
    float* out = (float*)d_out;

    __nv_bfloat16 *wcat, *wob, *thetab, *phiPb, *gPb, *agb;
    float* bcat;
    cudaGetSymbolAddress((void**)&wcat,   g_wcat);
    cudaGetSymbolAddress((void**)&bcat,   g_bcat);
    cudaGetSymbolAddress((void**)&wob,    g_wob);
    cudaGetSymbolAddress((void**)&thetab, g_thetab);
    cudaGetSymbolAddress((void**)&phiPb,  g_phiPb);
    cudaGetSymbolAddress((void**)&gPb,    g_gPb);
    cudaGetSymbolAddress((void**)&agb,    g_agb);

    cudaFuncSetAttribute(fattn_k, cudaFuncAttributeMaxDynamicSharedMemorySize, FATTN_SMEM);

    prep_k<<<768, 256>>>(w_theta, w_phi, w_g, b_theta, b_phi, b_g, w_o, wcat, bcat, wob);

    proj_k<<<dim3(3, NPIX / 128), 256>>>(x, wcat, bcat, thetab, phiPb, gPb);

    fattn_k<<<dim3(NQ / 64, NB), 256, FATTN_SMEM>>>(thetab, phiPb, gPb, agb);

    outp_k<<<dim3(4, NPIX / 128), 256>>>(agb, wob, b_o, out, x, sigma);
}

// round 15
// speedup vs baseline: 1.0386x; 1.0386x over previous
#include <cuda_runtime.h>
#include <cuda_bf16.h>
#include <cstdint>

#define NB   16
#define CIN  512
#define NQ   4096
#define NPIX (NB*NQ)
#define NKEY 1024
#define DQK  64
#define DV   256
#define NCAT 384

// ---------------- scratch ----------------
__device__ __nv_bfloat16 g_wcat [CIN*NCAT];
__device__ float         g_bcat [NCAT];
__device__ __nv_bfloat16 g_wob  [DV*CIN];
__device__ __nv_bfloat16 g_thetab[NPIX*DQK];
__device__ __nv_bfloat16 g_phiPb [NB*NKEY*DQK];
__device__ __nv_bfloat16 g_gPb   [NB*NKEY*DV];
__device__ __nv_bfloat16 g_agb   [NPIX*DV];

// ---------------- PTX helpers ----------------
__device__ __forceinline__ uint32_t smem_u32(const void* p) {
    return (uint32_t)__cvta_generic_to_shared(p);
}
__device__ __forceinline__ void ldsm_x4(uint32_t& r0, uint32_t& r1, uint32_t& r2, uint32_t& r3, uint32_t a) {
    asm volatile("ldmatrix.sync.aligned.m8n8.x4.shared.b16 {%0,%1,%2,%3},[%4];\n"
                 : "=r"(r0), "=r"(r1), "=r"(r2), "=r"(r3) : "r"(a));
}
__device__ __forceinline__ void ldsm_x4t(uint32_t& r0, uint32_t& r1, uint32_t& r2, uint32_t& r3, uint32_t a) {
    asm volatile("ldmatrix.sync.aligned.m8n8.x4.trans.shared.b16 {%0,%1,%2,%3},[%4];\n"
                 : "=r"(r0), "=r"(r1), "=r"(r2), "=r"(r3) : "r"(a));
}
__device__ __forceinline__ void mma_bf16(float* c, const uint32_t* a, const uint32_t* b) {
    asm volatile("mma.sync.aligned.m16n8k16.row.col.f32.bf16.bf16.f32 "
                 "{%0,%1,%2,%3},{%4,%5,%6,%7},{%8,%9},{%0,%1,%2,%3};\n"
                 : "+f"(c[0]), "+f"(c[1]), "+f"(c[2]), "+f"(c[3])
                 : "r"(a[0]), "r"(a[1]), "r"(a[2]), "r"(a[3]), "r"(b[0]), "r"(b[1]));
}
__device__ __forceinline__ void cp16(uint32_t dst, const void* src) {
    asm volatile("cp.async.ca.shared.global [%0],[%1],16;\n" :: "r"(dst), "l"(src));
}
__device__ __forceinline__ void cp8(uint32_t dst, const void* src) {
    asm volatile("cp.async.ca.shared.global [%0],[%1],8;\n" :: "r"(dst), "l"(src));
}
__device__ __forceinline__ void cp_commit() { asm volatile("cp.async.commit_group;\n" ::: "memory"); }
__device__ __forceinline__ void cp_wait0()  { asm volatile("cp.async.wait_group 0;\n" ::: "memory"); }

// ---------------- weight prep: concat + bf16 ----------------
__global__ void prep_k(const float* __restrict__ wt, const float* __restrict__ wp,
                       const float* __restrict__ wg, const float* __restrict__ bt,
                       const float* __restrict__ bp, const float* __restrict__ bg,
                       const float* __restrict__ wo,
                       __nv_bfloat16* __restrict__ wcat, float* __restrict__ bcat,
                       __nv_bfloat16* __restrict__ wob)
{
    int i = blockIdx.x * 256 + threadIdx.x;
    if (i < CIN * NCAT) {
        int r = i / NCAT, c = i % NCAT;
        float v = (c < 64) ? wt[r * 64 + c] : (c < 128 ? wp[r * 64 + c - 64] : wg[r * 256 + c - 128]);
        wcat[i] = __float2bfloat16(v);
    }
    if (i < NCAT) bcat[i] = (i < 64) ? bt[i] : (i < 128 ? bp[i - 64] : bg[i - 128]);
    if (i < DV * CIN) wob[i] = __float2bfloat16(wo[i]);
}

// ---------------- fused projection GEMM + bias + pool ----------------
#define P_ASTR 40
#define P_WSTR 136
#define P_TS   136

__global__ void __launch_bounds__(256) proj_k(
    const float* __restrict__ X, const __nv_bfloat16* __restrict__ Wc,
    const float* __restrict__ bcat, __nv_bfloat16* __restrict__ thetab,
    __nv_bfloat16* __restrict__ phiPb, __nv_bfloat16* __restrict__ gPb)
{
    constexpr int BK = 32;
    __shared__ __align__(16) __nv_bfloat16 sm[2 * 128 * P_ASTR + 2 * BK * P_WSTR];
    __nv_bfloat16* As[2] = { sm, sm + 128 * P_ASTR };
    __nv_bfloat16* Ws[2] = { sm + 2 * 128 * P_ASTR, sm + 2 * 128 * P_ASTR + BK * P_WSTR };
    __nv_bfloat16* T = sm;

    const int tid = threadIdx.x, lane = tid & 31, wid = tid >> 5;
    const int wr = wid >> 2, wc = wid & 3;
    const int bn = blockIdx.x * 128;
    const int bm = blockIdx.y * 128;

    const int arow = tid >> 1, aq = (tid & 1) * 16;
    const float* Ap = X + (size_t)(bm + arow) * CIN + aq;
    const int wrow = tid >> 4, wcol = (tid & 15) * 8;
    const __nv_bfloat16* Wp = Wc + (size_t)wrow * NCAT + bn + wcol;

    uint32_t as_u[2] = { smem_u32(As[0]), smem_u32(As[1]) };
    uint32_t ws_u[2] = { smem_u32(Ws[0]), smem_u32(Ws[1]) };

    float4 ar[4];
    float acc[4][4][4];
#pragma unroll
    for (int mt = 0; mt < 4; mt++)
#pragma unroll
        for (int nt = 0; nt < 4; nt++)
#pragma unroll
            for (int i = 0; i < 4; i++) acc[mt][nt][i] = 0.f;

    auto ldgA = [&](int it) {
#pragma unroll
        for (int j = 0; j < 4; j++) ar[j] = *(const float4*)(Ap + it * BK + j * 4);
    };
    auto stsA = [&](int s) {
#pragma unroll
        for (int j = 0; j < 4; j++) {
            __nv_bfloat162 lo = __floats2bfloat162_rn(ar[j].x, ar[j].y);
            __nv_bfloat162 hi = __floats2bfloat162_rn(ar[j].z, ar[j].w);
            *(uint2*)&As[s][arow * P_ASTR + aq + j * 4] =
                make_uint2(*(uint32_t*)&lo, *(uint32_t*)&hi);
        }
    };
    auto cpW = [&](int s, int it) {
        const __nv_bfloat16* src = Wp + (size_t)it * BK * NCAT;
        cp16(ws_u[s] + (wrow * P_WSTR + wcol) * 2, src);
        cp16(ws_u[s] + ((wrow + 16) * P_WSTR + wcol) * 2, src + (size_t)16 * NCAT);
    };
    auto compute = [&](int s) {
#pragma unroll
        for (int ks = 0; ks < 2; ks++) {
            uint32_t af[4][4], bfr[4][2];
#pragma unroll
            for (int mt = 0; mt < 4; mt++)
                ldsm_x4(af[mt][0], af[mt][1], af[mt][2], af[mt][3],
                        as_u[s] + ((wr * 64 + mt * 16 + (lane & 15)) * P_ASTR + ks * 16 + (lane >> 4) * 8) * 2);
#pragma unroll
            for (int ntp = 0; ntp < 2; ntp++)
                ldsm_x4t(bfr[2*ntp][0], bfr[2*ntp][1], bfr[2*ntp+1][0], bfr[2*ntp+1][1],
                         ws_u[s] + ((ks * 16 + (lane & 15)) * P_WSTR + wc * 32 + ntp * 16 + (lane >> 4) * 8) * 2);
#pragma unroll
            for (int mt = 0; mt < 4; mt++)
#pragma unroll
                for (int nt = 0; nt < 4; nt++)
                    mma_bf16(acc[mt][nt], af[mt], bfr[nt]);
        }
    };

    constexpr int nIt = CIN / BK;
    ldgA(0); cpW(0, 0); cp_commit(); stsA(0);
    cp_wait0(); __syncthreads();
    for (int it = 0; it < nIt; it++) {
        int cur = it & 1, nx = cur ^ 1;
        bool more = (it + 1 < nIt);
        if (more) { ldgA(it + 1); cpW(nx, it + 1); cp_commit(); }
        compute(cur);
        if (more) { stsA(nx); cp_wait0(); __syncthreads(); }
    }
    __syncthreads();

#pragma unroll
    for (int mt = 0; mt < 4; mt++) {
        int r0 = wr * 64 + mt * 16 + (lane >> 2);
#pragma unroll
        for (int nt = 0; nt < 4; nt++) {
            int col = wc * 32 + nt * 8 + (lane & 3) * 2;
            float b0 = bcat[bn + col], b1 = bcat[bn + col + 1];
            *(__nv_bfloat162*)&T[r0 * P_TS + col] =
                __floats2bfloat162_rn(acc[mt][nt][0] + b0, acc[mt][nt][1] + b1);
            *(__nv_bfloat162*)&T[(r0 + 8) * P_TS + col] =
                __floats2bfloat162_rn(acc[mt][nt][2] + b0, acc[mt][nt][3] + b1);
        }
    }
    __syncthreads();

    const int b  = bm >> 12;
    const int h2 = (bm & 4095) >> 7;
    const size_t keyb = (size_t)b * NKEY + h2 * 32;

    if (bn == 0) {
#pragma unroll
        for (int i = 0; i < 4; i++) {
            int e = tid + i * 256, row = e >> 3, c = (e & 7) * 8;
            *(uint4*)(thetab + (size_t)(bm + row) * DQK + c) = *(uint4*)&T[row * P_TS + c];
        }
#pragma unroll
        for (int i = 0; i < 8; i++) {
            int e = tid + i * 256, w2 = e >> 6, c = e & 63;
            int col = 64 + c, r0 = 2 * w2;
            float v0 = __bfloat162float(T[r0 * P_TS + col]);
            float v1 = __bfloat162float(T[(r0 + 1) * P_TS + col]);
            float v2 = __bfloat162float(T[(r0 + 64) * P_TS + col]);
            float v3 = __bfloat162float(T[(r0 + 65) * P_TS + col]);
            phiPb[(keyb + w2) * DQK + c] = __float2bfloat16(fmaxf(fmaxf(v0, v1), fmaxf(v2, v3)));
        }
    } else {
        int gc0 = bn - 128;
#pragma unroll
        for (int i = 0; i < 16; i++) {
            int e = tid + i * 256, w2 = e >> 7, c = e & 127;
            int r0 = 2 * w2;
            float v0 = __bfloat162float(T[r0 * P_TS + c]);
            float v1 = __bfloat162float(T[(r0 + 1) * P_TS + c]);
            float v2 = __bfloat162float(T[(r0 + 64) * P_TS + c]);
            float v3 = __bfloat162float(T[(r0 + 65) * P_TS + c]);
            gPb[(keyb + w2) * DV + gc0 + c] = __float2bfloat16(fmaxf(fmaxf(v0, v1), fmaxf(v2, v3)));
        }
    }
}

// ---------------- out-projection GEMM + residual epilogue ----------------
__global__ void __launch_bounds__(256, 2) outp_k(
    const __nv_bfloat16* __restrict__ A, const __nv_bfloat16* __restrict__ W,
    const float* __restrict__ bias, float* __restrict__ Out,
    const float* __restrict__ X, const float* __restrict__ sigma)
{
    constexpr int BK = 32, N = CIN, K = DV;
    __shared__ __align__(16) __nv_bfloat16 As[2][128 * P_ASTR];
    __shared__ __align__(16) __nv_bfloat16 Ws[2][BK * P_WSTR];

    const int tid = threadIdx.x, lane = tid & 31, wid = tid >> 5;
    const int wr = wid >> 2, wc = wid & 3;
    const int bn = blockIdx.x * 128;
    const int bm = blockIdx.y * 128;

    const int wrow = tid >> 4, wcol = (tid & 15) * 8;
    const __nv_bfloat16* Wp = W + (size_t)wrow * N + bn + wcol;

    uint32_t as_u[2] = { smem_u32(As[0]), smem_u32(As[1]) };
    uint32_t ws_u[2] = { smem_u32(Ws[0]), smem_u32(Ws[1]) };

    float acc[4][4][4];
#pragma unroll
    for (int mt = 0; mt < 4; mt++)
#pragma unroll
        for (int nt = 0; nt < 4; nt++)
#pragma unroll
            for (int i = 0; i < 4; i++) acc[mt][nt][i] = 0.f;

    auto cpA = [&](int s, int it) {
#pragma unroll
        for (int i = 0; i < 4; i++) {
            int ci = tid + i * 256, row = ci >> 3, c4 = (ci & 7) * 4;
            cp8(as_u[s] + (row * P_ASTR + c4) * 2,
                A + (size_t)(bm + row) * K + it * BK + c4);
        }
    };
    auto cpW = [&](int s, int it) {
        const __nv_bfloat16* src = Wp + (size_t)it * BK * N;
        cp16(ws_u[s] + (wrow * P_WSTR + wcol) * 2, src);
        cp16(ws_u[s] + ((wrow + 16) * P_WSTR + wcol) * 2, src + (size_t)16 * N);
    };
    auto compute = [&](int s) {
#pragma unroll
        for (int ks = 0; ks < 2; ks++) {
            uint32_t af[4][4], bfr[4][2];
#pragma unroll
            for (int mt = 0; mt < 4; mt++)
                ldsm_x4(af[mt][0], af[mt][1], af[mt][2], af[mt][3],
                        as_u[s] + ((wr * 64 + mt * 16 + (lane & 15)) * P_ASTR + ks * 16 + (lane >> 4) * 8) * 2);
#pragma unroll
            for (int ntp = 0; ntp < 2; ntp++)
                ldsm_x4t(bfr[2*ntp][0], bfr[2*ntp][1], bfr[2*ntp+1][0], bfr[2*ntp+1][1],
                         ws_u[s] + ((ks * 16 + (lane & 15)) * P_WSTR + wc * 32 + ntp * 16 + (lane >> 4) * 8) * 2);
#pragma unroll
            for (int mt = 0; mt < 4; mt++)
#pragma unroll
                for (int nt = 0; nt < 4; nt++)
                    mma_bf16(acc[mt][nt], af[mt], bfr[nt]);
        }
    };

    constexpr int nIt = K / BK;
    cpA(0, 0); cpW(0, 0); cp_commit();
    cp_wait0(); __syncthreads();
    for (int it = 0; it < nIt; it++) {
        int cur = it & 1, nx = cur ^ 1;
        bool more = (it + 1 < nIt);
        if (more) { cpA(nx, it + 1); cpW(nx, it + 1); cp_commit(); }
        compute(cur);
        if (more) { cp_wait0(); __syncthreads(); }
    }

    const float s = sigma[0];
#pragma unroll
    for (int mt = 0; mt < 4; mt++) {
        int r0 = bm + wr * 64 + mt * 16 + (lane >> 2);
        float2 xv[4][2];
#pragma unroll
        for (int nt = 0; nt < 4; nt++) {
            int col = bn + wc * 32 + nt * 8 + (lane & 3) * 2;
#pragma unroll
            for (int h = 0; h < 2; h++)
                xv[nt][h] = *(const float2*)(X + (size_t)(r0 + h * 8) * N + col);
        }
#pragma unroll
        for (int nt = 0; nt < 4; nt++) {
            int col = bn + wc * 32 + nt * 8 + (lane & 3) * 2;
            float b0 = bias[col], b1 = bias[col + 1];
#pragma unroll
            for (int h = 0; h < 2; h++) {
                size_t off = (size_t)(r0 + h * 8) * N + col;
                *(float2*)(Out + off) = make_float2(xv[nt][h].x + s * (acc[mt][nt][2 * h] + b0),
                                                    xv[nt][h].y + s * (acc[mt][nt][2 * h + 1] + b1));
            }
        }
    }
}

// ---------------- flash attention: no-max softmax, 2 syncs/iter (R7) ----------------
#define F_PH0   9216
#define F_G0    27648
#define F_GSZ   33792
#define F_PSUM  95232
#define F_LINV  95744
#define FATTN_SMEM 96000

__global__ void __launch_bounds__(256, 2) fattn_k(
    const __nv_bfloat16* __restrict__ theta, const __nv_bfloat16* __restrict__ phiP,
    const __nv_bfloat16* __restrict__ gP, __nv_bfloat16* __restrict__ outg)
{
    extern __shared__ char smc[];
    __nv_bfloat16* Ps = (__nv_bfloat16*)smc;
    float* psum = (float*)(smc + F_PSUM);
    float* linv = (float*)(smc + F_LINV);
    const uint32_t ps_u = smem_u32(smc);
    const uint32_t ph_u[2] = { ps_u + F_PH0, ps_u + F_PH0 + 9216 };
    const uint32_t gs_u[2] = { ps_u + F_G0,  ps_u + F_G0 + F_GSZ };

    const int b = blockIdx.y, q0 = blockIdx.x * 64;
    const int tid = threadIdx.x, lane = tid & 31, wid = tid >> 5;
    const int wr = wid & 3;
    const int wg = wid >> 2;
    const int vc = wid * 32;

    const __nv_bfloat16* phb = phiP + (size_t)b * NKEY * DQK;
    const __nv_bfloat16* gb  = gP   + (size_t)b * NKEY * DV;

#pragma unroll
    for (int i = 0; i < 2; i++) {
        int c = tid + i * 256, row = c >> 3, c8 = (c & 7) * 8;
        *(uint4*)&Ps[row * 72 + c8] =
            *(const uint4*)(theta + ((size_t)b * NQ + q0 + row) * DQK + c8);
    }
    __syncthreads();

    uint32_t af[4][4];
#pragma unroll
    for (int ks = 0; ks < 4; ks++)
        ldsm_x4(af[ks][0], af[ks][1], af[ks][2], af[ks][3],
                ps_u + ((wr * 16 + (lane & 15)) * 72 + ks * 16 + (lane >> 4) * 8) * 2);

    auto ldPhi = [&](int buf, int kt) {
#pragma unroll
        for (int i = 0; i < 2; i++) {
            int c = tid + i * 256, row = c >> 3, c8 = (c & 7) * 8;
            cp16(ph_u[buf] + (row * 72 + c8) * 2, phb + (size_t)(kt * 64 + row) * DQK + c8);
        }
    };
    auto ldG = [&](int buf, int kt) {
#pragma unroll
        for (int i = 0; i < 8; i++) {
            int c = tid + i * 256, row = c >> 5, c8 = (c & 31) * 8;
            cp16(gs_u[buf] + (row * 264 + c8) * 2, gb + (size_t)(kt * 64 + row) * DV + c8);
        }
    };

    float l0 = 0.f, l1 = 0.f;
    float acc[4][4][4];
#pragma unroll
    for (int mt = 0; mt < 4; mt++)
#pragma unroll
        for (int nt = 0; nt < 4; nt++)
#pragma unroll
            for (int i = 0; i < 4; i++) acc[mt][nt][i] = 0.f;

    const int row0 = wr * 16 + (lane >> 2);
    const int prow = lane >> 2;

    ldPhi(0, 0); ldG(0, 0); cp_commit();

    for (int kt = 0; kt < 16; kt++) {
        const int cur = kt & 1, nx = cur ^ 1;
        cp_wait0();
        __syncthreads();
        if (kt < 15) { ldPhi(nx, kt + 1); ldG(nx, kt + 1); cp_commit(); }

        // ---- S = theta @ phi^T : warp's 16 rows x 32 key-cols (x4-merged B loads) ----
        float sacc[4][4];
#pragma unroll
        for (int nt = 0; nt < 4; nt++)
#pragma unroll
            for (int i = 0; i < 4; i++) sacc[nt][i] = 0.f;
#pragma unroll
        for (int ks = 0; ks < 4; ks++) {
#pragma unroll
            for (int ntp = 0; ntp < 2; ntp++) {
                uint32_t b0, b1, b2, b3;
                int nrow = wg * 32 + ntp * 16 + (lane >> 4) * 8 + (lane & 7);
                int dcol = ks * 16 + ((lane >> 3) & 1) * 8;
                ldsm_x4(b0, b1, b2, b3, ph_u[cur] + (nrow * 72 + dcol) * 2);
                uint32_t bl[2] = { b0, b1 }, bh[2] = { b2, b3 };
                mma_bf16(sacc[2*ntp],     af[ks], bl);
                mma_bf16(sacc[2*ntp + 1], af[ks], bh);
            }
        }

#pragma unroll
        for (int nt = 0; nt < 4; nt++) {
            float p0 = __expf(sacc[nt][0]), p1 = __expf(sacc[nt][1]);
            float p2 = __expf(sacc[nt][2]), p3 = __expf(sacc[nt][3]);
            l0 += p0 + p1; l1 += p2 + p3;
            int col = wg * 32 + nt * 8 + (lane & 3) * 2;
            *(__nv_bfloat162*)&Ps[row0 * 72 + col]       = __floats2bfloat162_rn(p0, p1);
            *(__nv_bfloat162*)&Ps[(row0 + 8) * 72 + col] = __floats2bfloat162_rn(p2, p3);
        }
        __syncthreads();

        // ---- O += P @ g : all 64 rows x this warp's 32 value-cols (x4t-merged) ----
#pragma unroll
        for (int ks = 0; ks < 4; ks++) {
            uint32_t aP[4][4];
#pragma unroll
            for (int mt = 0; mt < 4; mt++)
                ldsm_x4(aP[mt][0], aP[mt][1], aP[mt][2], aP[mt][3],
                        ps_u + ((mt * 16 + (lane & 15)) * 72 + ks * 16 + (lane >> 4) * 8) * 2);
#pragma unroll
            for (int ntp = 0; ntp < 2; ntp++) {
                uint32_t g0, g1, g2, g3;
                ldsm_x4t(g0, g1, g2, g3,
                         gs_u[cur] + ((ks * 16 + (lane & 15)) * 264 + vc + ntp * 16 + (lane >> 4) * 8) * 2);
                uint32_t bl[2] = { g0, g1 }, bh[2] = { g2, g3 };
#pragma unroll
                for (int mt = 0; mt < 4; mt++) {
                    mma_bf16(acc[mt][2*ntp],     aP[mt], bl);
                    mma_bf16(acc[mt][2*ntp + 1], aP[mt], bh);
                }
            }
        }
    }

    l0 += __shfl_xor_sync(0xffffffffu, l0, 1);
    l0 += __shfl_xor_sync(0xffffffffu, l0, 2);
    l1 += __shfl_xor_sync(0xffffffffu, l1, 1);
    l1 += __shfl_xor_sync(0xffffffffu, l1, 2);
    if ((lane & 3) == 0) {
        psum[wg * 64 + row0]     = l0;
        psum[wg * 64 + row0 + 8] = l1;
    }
    __syncthreads();
    if (tid < 64) linv[tid] = 1.f / (psum[tid] + psum[64 + tid]);
    __syncthreads();

    const size_t rb = (size_t)b * NQ + q0;
#pragma unroll
    for (int mt = 0; mt < 4; mt++) {
        float inv0 = linv[mt * 16 + prow], inv1 = linv[mt * 16 + prow + 8];
        int r = mt * 16 + prow;
#pragma unroll
        for (int nt = 0; nt < 4; nt++) {
            int col = vc + nt * 8 + (lane & 3) * 2;
            *(__nv_bfloat162*)&outg[(rb + r) * DV + col] =
                __floats2bfloat162_rn(acc[mt][nt][0] * inv0, acc[mt][nt][1] * inv0);
            *(__nv_bfloat162*)&outg[(rb + r + 8) * DV + col] =
                __floats2bfloat162_rn(acc[mt][nt][2] * inv1, acc[mt][nt][3] * inv1);
        }
    }
}

// ---------------- launch ----------------
extern "C" void kernel_launch(void* const* d_in, const int* in_sizes, int n_in,
                              void* d_out, int out_size)
{
    const float* x       = (const float*)d_in[0];
    const float* w_theta = (const float*)d_in[1];
    const float* b_theta = (const float*)d_in[2];
    const float* w_phi   = (const float*)d_in[3];
    const float* b_phi   = (const float*)d_in[4];
    const float* w_g     = (const float*)d_in[5];
    const float* b_g     = (const float*)d_in[6];
    const float* w_o     = (const float*)d_in[7];
    const float* b_o     = (const float*)d_in[8];
    const float* sigma   = (const float*)d_in[9];
    float* out = (float*)d_out;

    __nv_bfloat16 *wcat, *wob, *thetab, *phiPb, *gPb, *agb;
    float* bcat;
    cudaGetSymbolAddress((void**)&wcat,   g_wcat);
    cudaGetSymbolAddress((void**)&bcat,   g_bcat);
    cudaGetSymbolAddress((void**)&wob,    g_wob);
    cudaGetSymbolAddress((void**)&thetab, g_thetab);
    cudaGetSymbolAddress((void**)&phiPb,  g_phiPb);
    cudaGetSymbolAddress((void**)&gPb,    g_gPb);
    cudaGetSymbolAddress((void**)&agb,    g_agb);

    cudaFuncSetAttribute(fattn_k, cudaFuncAttributeMaxDynamicSharedMemorySize, FATTN_SMEM);

    prep_k<<<768, 256>>>(w_theta, w_phi, w_g, b_theta, b_phi, b_g, w_o, wcat, bcat, wob);

    proj_k<<<dim3(3, NPIX / 128), 256>>>(x, wcat, bcat, thetab, phiPb, gPb);

    fattn_k<<<dim3(NQ / 64, NB), 256, FATTN_SMEM>>>(thetab, phiPb, gPb, agb);

    outp_k<<<dim3(4, NPIX / 128), 256>>>(agb, wob, b_o, out, x, sigma);
}